// round 10
// baseline (speedup 1.0000x reference)
#include <cuda_runtime.h>
#include <math.h>
#include <stdint.h>

// Problem constants
#define B_SZ   8
#define C_SZ   256
#define H_SZ   64
#define W_SZ   64
#define PIX    4096          // H*W
#define L_TOT  32768         // B*H*W
#define HEADS  4
#define WIN    256           // window size (positions)
#define NWIN   128           // windows per branch (B*16)
#define SCALE  0.125f        // (256/4)^-0.5
#define LN_EPS 1e-4f

#define OUT_ELEMS  ((size_t)B_SZ * C_SZ * PIX)          // 8388608
#define ATTN_ELEMS ((size_t)NWIN * HEADS * WIN * WIN)   // 8388608

// Scratch (device globals — no allocation allowed)
__device__ float    g_xn[(size_t)B_SZ * C_SZ * PIX];       // LN out (tf32 bits)
__device__ float    g_qkv[(size_t)B_SZ * 3 * C_SZ * PIX];  // qkv (window-major for ch<128)
__device__ float    g_xcat[(size_t)B_SZ * C_SZ * PIX];     // attn out (tf32 bits)
__device__ uint32_t g_wq[768 * 256];                       // W_qkv tf32, k-pair permuted
__device__ uint32_t g_wp[256 * 256];                       // W_proj tf32, k-pair permuted

// ---------------------------------------------------------------------------
__device__ __forceinline__ uint32_t f2tf(float f) {
    uint32_t r;
    asm("cvt.rna.tf32.f32 %0, %1;" : "=r"(r) : "f"(f));
    return r;
}

__device__ __forceinline__ void mma_tf32(float* d, const uint32_t* a, const uint32_t* b) {
    asm("mma.sync.aligned.m16n8k8.row.col.f32.tf32.tf32.f32 "
        "{%0,%1,%2,%3},{%4,%5,%6,%7},{%8,%9},{%0,%1,%2,%3};"
        : "+f"(d[0]), "+f"(d[1]), "+f"(d[2]), "+f"(d[3])
        : "r"(a[0]), "r"(a[1]), "r"(a[2]), "r"(a[3]), "r"(b[0]), "r"(b[1]));
}

__device__ __forceinline__ void cp16(void* dst, const void* src) {
    uint32_t d = (uint32_t)__cvta_generic_to_shared(dst);
    asm volatile("cp.async.cg.shared.global [%0], [%1], 16;" :: "r"(d), "l"(src));
}
__device__ __forceinline__ void cp_commit() {
    asm volatile("cp.async.commit_group;");
}

// ---------------------------------------------------------------------------
// Weight prep: tf32 convert + k-pair permutation (phys c <- logical l)
// ---------------------------------------------------------------------------
__global__ void wprep(const float* __restrict__ wqkv, const float* __restrict__ wproj,
                      uint32_t* __restrict__ wq, uint32_t* __restrict__ wp) {
    int idx = blockIdx.x * 256 + threadIdx.x;
    int j = idx >> 8, c = idx & 255;
    int l = (c & ~7) + ((c >> 1) & 3) + (c & 1) * 4;
    if (j < 768) wq[idx] = f2tf(wqkv[j * 256 + l]);
    else         wp[(j - 768) * 256 + c] = f2tf(wproj[(j - 768) * 256 + l]);
}

// ---------------------------------------------------------------------------
// LayerNorm over C per pixel, vectorized. Block = 64 pixels, 256 threads.
// Thread (cg, x4): channels cg*16..cg*16+15, pixel-float4 x4. Emits tf32 bits.
// ---------------------------------------------------------------------------
__global__ __launch_bounds__(256)
void ln_kernel(const float* __restrict__ x,
               const float* __restrict__ g,
               const float* __restrict__ be,
               float* __restrict__ xnT) {
    int px0 = blockIdx.x * 64;
    int b   = px0 >> 12;
    int p0  = px0 & (PIX - 1);
    int t   = threadIdx.x;
    int x4  = t & 15;        // pixel float4 index (0..15)
    int cg  = t >> 4;        // channel group (0..15)

    const float4* xb = (const float4*)(x + (size_t)b * C_SZ * PIX + p0);
    float4 v[16];
    float4 sum = make_float4(0.f, 0.f, 0.f, 0.f);
    float4 sq  = make_float4(0.f, 0.f, 0.f, 0.f);
#pragma unroll
    for (int i = 0; i < 16; i++) {
        int c = cg * 16 + i;
        float4 tv = xb[(size_t)c * (PIX / 4) + x4];
        v[i] = tv;
        sum.x += tv.x; sum.y += tv.y; sum.z += tv.z; sum.w += tv.w;
        sq.x += tv.x * tv.x; sq.y += tv.y * tv.y;
        sq.z += tv.z * tv.z; sq.w += tv.w * tv.w;
    }
    __shared__ float4 rs1[16][16], rs2[16][16];
    __shared__ float4 mu4[16], rv4[16];
    rs1[cg][x4] = sum;
    rs2[cg][x4] = sq;
    __syncthreads();
    if (t < 16) {
        float4 s1 = make_float4(0.f, 0.f, 0.f, 0.f);
        float4 s2 = make_float4(0.f, 0.f, 0.f, 0.f);
#pragma unroll
        for (int k = 0; k < 16; k++) {
            float4 a = rs1[k][t], bb = rs2[k][t];
            s1.x += a.x; s1.y += a.y; s1.z += a.z; s1.w += a.w;
            s2.x += bb.x; s2.y += bb.y; s2.z += bb.z; s2.w += bb.w;
        }
        float4 mu = make_float4(s1.x / C_SZ, s1.y / C_SZ, s1.z / C_SZ, s1.w / C_SZ);
        mu4[t] = mu;
        rv4[t] = make_float4(rsqrtf(s2.x / C_SZ - mu.x * mu.x + LN_EPS),
                             rsqrtf(s2.y / C_SZ - mu.y * mu.y + LN_EPS),
                             rsqrtf(s2.z / C_SZ - mu.z * mu.z + LN_EPS),
                             rsqrtf(s2.w / C_SZ - mu.w * mu.w + LN_EPS));
    }
    __syncthreads();
    float4 mu = mu4[x4], rv = rv4[x4];
    float4* ob = (float4*)(xnT + (size_t)b * C_SZ * PIX + p0);
#pragma unroll
    for (int i = 0; i < 16; i++) {
        int c = cg * 16 + i;
        float gc = g[c], bc = be[c];
        float4 tv = v[i];
        float4 o;
        o.x = __uint_as_float(f2tf((tv.x - mu.x) * rv.x * gc + bc));
        o.y = __uint_as_float(f2tf((tv.y - mu.y) * rv.y * gc + bc));
        o.z = __uint_as_float(f2tf((tv.z - mu.z) * rv.z * gc + bc));
        o.w = __uint_as_float(f2tf((tv.w - mu.w) * rv.w * gc + bc));
        ob[(size_t)c * (PIX / 4) + x4] = o;
    }
}

// ---------------------------------------------------------------------------
// tf32 GEMM: CTA 128(j) x 128(pix), 128 threads, 3-stage cp.async, 2 CTA/SM.
// permq tiles: stage output in smem, write window-major as full 32B sectors.
// ---------------------------------------------------------------------------
#define ASTR 40
#define BSTR 136
#define STAGE_A (128 * ASTR)
#define STAGE_B (32 * BSTR)

__global__ __launch_bounds__(128, 2)
void gemm_tf32(const uint32_t* __restrict__ ATu,
               const uint32_t* __restrict__ Wu,
               const float* __restrict__ bias,
               float* __restrict__ outT,
               int CA, int CO, int hasb, int permq) {
    extern __shared__ uint32_t smu[];
    uint32_t* As = smu;                    // 3 stages
    uint32_t* Bs = smu + 3 * STAGE_A;      // 3 stages

    int tid = threadIdx.x;
    int j0  = blockIdx.x * 128;
    int l0  = blockIdx.y * 128;
    int b   = l0 >> 12;
    int p0  = l0 & (PIX - 1);

    const uint32_t* Ab = ATu + (size_t)b * CA * PIX + p0;
    int lane = tid & 31;
    int w    = tid >> 5;
    int wm   = w & 1;
    int wn   = w >> 1;
    int r    = lane >> 2;
    int qk   = lane & 3;

    int brow = tid >> 2, bcol = (tid & 3) * 32;

    float d[4][8][4];
#pragma unroll
    for (int mt = 0; mt < 4; mt++)
#pragma unroll
        for (int nt = 0; nt < 8; nt++)
#pragma unroll
            for (int i = 0; i < 4; i++) d[mt][nt][i] = 0.f;

    const int NC = CA / 32;

    auto issue = [&](int c0, int buf) {
        uint32_t* Ad = As + buf * STAGE_A + tid * ASTR;
        const uint32_t* Asrc = Wu + (size_t)(j0 + tid) * CA + c0;
#pragma unroll
        for (int i = 0; i < 8; i++) cp16(Ad + i * 4, Asrc + i * 4);
        uint32_t* Bd = Bs + buf * STAGE_B + brow * BSTR + bcol;
        const uint32_t* Bsrc = Ab + (size_t)(c0 + brow) * PIX + bcol;
#pragma unroll
        for (int i = 0; i < 8; i++) cp16(Bd + i * 4, Bsrc + i * 4);
        cp_commit();
    };

    issue(0, 0);
    if (NC > 1) issue(32, 1);

    for (int ic = 0; ic < NC; ic++) {
        if (ic + 2 < NC) {
            issue((ic + 2) * 32, (ic + 2) % 3);
            asm volatile("cp.async.wait_group 2;");
        } else if (ic + 1 < NC) {
            asm volatile("cp.async.wait_group 1;");
        } else {
            asm volatile("cp.async.wait_group 0;");
        }
        __syncthreads();

        const uint32_t* Abs = As + (ic % 3) * STAGE_A;
        const uint32_t* Bbs = Bs + (ic % 3) * STAGE_B;
#pragma unroll
        for (int ks = 0; ks < 4; ks++) {
            int kk8 = ks * 8;
            uint32_t afr[4][4];
#pragma unroll
            for (int mt = 0; mt < 4; mt++) {
                int m0 = wm * 64 + mt * 16 + r;
                uint2 u0 = *(const uint2*)&Abs[m0 * ASTR + kk8 + 2 * qk];
                uint2 u1 = *(const uint2*)&Abs[(m0 + 8) * ASTR + kk8 + 2 * qk];
                afr[mt][0] = u0.x; afr[mt][1] = u1.x;
                afr[mt][2] = u0.y; afr[mt][3] = u1.y;
            }
            uint32_t bfr[8][2];
#pragma unroll
            for (int nt = 0; nt < 8; nt++) {
                int n = wn * 64 + nt * 8 + r;
                bfr[nt][0] = Bbs[(kk8 + qk) * BSTR + n];
                bfr[nt][1] = Bbs[(kk8 + qk + 4) * BSTR + n];
            }
#pragma unroll
            for (int mt = 0; mt < 4; mt++)
#pragma unroll
                for (int nt = 0; nt < 8; nt++)
                    mma_tf32(d[mt][nt], afr[mt], bfr[nt]);
        }
        __syncthreads();
    }

    int prm = permq && ((j0 & 128) == 0);   // lower-half channels -> branch-0 perm
    float* obase = outT + (size_t)b * CO * PIX;

    if (prm) {
        // ---- stage tile in smem [p_local][j_local] (stride 129), then write
        //      window-major: (j, colgrp) = 8 consecutive floats = 1 sector ----
        float* Sx = (float*)smu;   // 128*129 floats = 66KB, fits
        __syncthreads();
#pragma unroll
        for (int mt = 0; mt < 4; mt++) {
            int jl = wm * 64 + mt * 16 + r;
#pragma unroll
            for (int nt = 0; nt < 8; nt++) {
                int pl = wn * 64 + nt * 8 + qk * 2;
                Sx[pl * 129 + jl]           = d[mt][nt][0];
                Sx[(pl + 1) * 129 + jl]     = d[mt][nt][1];
                Sx[pl * 129 + jl + 8]       = d[mt][nt][2];
                Sx[(pl + 1) * 129 + jl + 8] = d[mt][nt][3];
            }
        }
        __syncthreads();
        int R = p0 >> 6;   // even global row base
        float* dstb = obase + (size_t)(j0 + tid) * PIX + R * 4;
#pragma unroll
        for (int cgp = 0; cgp < 16; cgp++) {
            float4 a, b4;
            a.x  = Sx[(cgp * 4 + 0) * 129 + tid];
            a.y  = Sx[(cgp * 4 + 1) * 129 + tid];
            a.z  = Sx[(cgp * 4 + 2) * 129 + tid];
            a.w  = Sx[(cgp * 4 + 3) * 129 + tid];
            b4.x = Sx[(64 + cgp * 4 + 0) * 129 + tid];
            b4.y = Sx[(64 + cgp * 4 + 1) * 129 + tid];
            b4.z = Sx[(64 + cgp * 4 + 2) * 129 + tid];
            b4.w = Sx[(64 + cgp * 4 + 3) * 129 + tid];
            *(float4*)(dstb + cgp * 256)     = a;
            *(float4*)(dstb + cgp * 256 + 4) = b4;
        }
    } else {
#pragma unroll
        for (int mt = 0; mt < 4; mt++) {
            int j = j0 + wm * 64 + mt * 16 + r;
            float bv0 = hasb ? bias[j]     : 0.f;
            float bv1 = hasb ? bias[j + 8] : 0.f;
#pragma unroll
            for (int nt = 0; nt < 8; nt++) {
                int p2 = p0 + wn * 64 + nt * 8 + qk * 2;
                float* o = obase + (size_t)j * PIX + p2;
                *(float2*)o = make_float2(d[mt][nt][0] + bv0, d[mt][nt][1] + bv0);
                *(float2*)(o + 8 * PIX) = make_float2(d[mt][nt][2] + bv1, d[mt][nt][3] + bv1);
            }
        }
    }
}

// ---------------------------------------------------------------------------
// Two-pass MMA attention + LePE (unchanged from round 9).
// dyn smem: Ks [256*40], Vs [32*264]  (~73KB)
// ---------------------------------------------------------------------------
#define KST 40
#define VST 264

__global__ __launch_bounds__(256, 2)
void attn_kernel(const float* __restrict__ qkvT,
                 const float* __restrict__ lw1,
                 const float* __restrict__ lb1,
                 const float* __restrict__ lw2,
                 const float* __restrict__ lb2,
                 float* __restrict__ xcat,
                 float* __restrict__ dout) {
    int br   = blockIdx.z;
    int hd   = blockIdx.y;
    int widx = blockIdx.x;
    int b    = widx >> 4;
    int wg   = widx & 15;
    int s    = threadIdx.x;
    int lane = s & 31;
    int w    = s >> 5;
    int r    = lane >> 2;
    int qk   = lane & 3;

    int hsp, wsp, p, rr0, cc0;
    if (br == 0) {
        hsp = 64; wsp = 4;
        rr0 = s >> 2; cc0 = s & 3;
        p = rr0 * W_SZ + wg * 4 + cc0;
    } else {
        hsp = 4; wsp = 64;
        rr0 = s >> 6; cc0 = s & 63;
        p = (wg * 4 + rr0) * W_SZ + cc0;
    }
    const float* lw = br ? lw2 : lw1;
    const float* lb = br ? lb2 : lb1;

    extern __shared__ uint32_t smA[];
    uint32_t* Ks = smA;                  // [256][40] pair-permuted cols (->Os)
    uint32_t* Vs = smA + 256 * KST;      // [32][264]
    __shared__ float lwsh[32][9];
    __shared__ float lbsh[32];

    size_t base = (size_t)b * 3 * C_SZ * PIX + wg * 256;

    // ---- coalesced K/V load (lane = 8*ci + si; conflict-free STS) ----
    {
        int ci = lane >> 3;
        int si = lane & 7;
#pragma unroll
        for (int g = 0; g < 8; g++) {
            int cc = 4 * g + ci;
            int ch = br * 128 + cc * 4 + hd;
            int sg = (cc & 24) + 2 * (cc & 3) + ((cc >> 2) & 1);  // K col perm
            const float* qp = qkvT + base + (size_t)ch * PIX;
#pragma unroll
            for (int u = 0; u < 4; u++) {
                int s2 = w * 32 + u * 8 + si;
                Ks[s2 * KST + sg] = f2tf(qp[(size_t)C_SZ * PIX + s2]);
                Vs[cc * VST + s2] = f2tf(qp[(size_t)(2 * C_SZ) * PIX + s2]);
            }
        }
    }
    for (int i = s; i < 32 * 9; i += 256) {
        int cc = i / 9, kk = i % 9;
        lwsh[cc][kk] = lw[(size_t)(cc * 4 + hd) * 9 + kk];
    }
    if (s < 32) lbsh[s] = lb[s * 4 + hd];

    // ---- Q fragments direct from gmem ----
    uint32_t qf[2][4][4];
#pragma unroll
    for (int ks = 0; ks < 4; ks++) {
        int kk = ks * 8 + qk;
        const float* q0 = qkvT + base + (size_t)(br * 128 + kk * 4 + hd) * PIX;
        const float* q1 = qkvT + base + (size_t)(br * 128 + (kk + 4) * 4 + hd) * PIX;
#pragma unroll
        for (int mt = 0; mt < 2; mt++) {
            int m0 = w * 32 + mt * 16 + r;
            qf[mt][ks][0] = f2tf(q0[m0] * SCALE);
            qf[mt][ks][1] = f2tf(q0[m0 + 8] * SCALE);
            qf[mt][ks][2] = f2tf(q1[m0] * SCALE);
            qf[mt][ks][3] = f2tf(q1[m0 + 8] * SCALE);
        }
    }
    __syncthreads();

    size_t abase = OUT_ELEMS + (size_t)br * ATTN_ELEMS
                 + (size_t)(widx * HEADS + hd) * WIN * WIN;

    // ---- pass A: row sums ----
    float rsm[2][2] = {{0.f, 0.f}, {0.f, 0.f}};
    for (int c0 = 0; c0 < WIN; c0 += 32) {
        float sacc[2][4][4];
#pragma unroll
        for (int mt = 0; mt < 2; mt++)
#pragma unroll
            for (int nt = 0; nt < 4; nt++)
#pragma unroll
                for (int i = 0; i < 4; i++) sacc[mt][nt][i] = 0.f;
#pragma unroll
        for (int ks = 0; ks < 4; ks++) {
            uint32_t bf[4][2];
#pragma unroll
            for (int nt = 0; nt < 4; nt++) {
                int n = c0 + nt * 8 + r;
                uint2 u = *(const uint2*)&Ks[n * KST + ks * 8 + 2 * qk];
                bf[nt][0] = u.x; bf[nt][1] = u.y;
            }
#pragma unroll
            for (int mt = 0; mt < 2; mt++)
#pragma unroll
                for (int nt = 0; nt < 4; nt++)
                    mma_tf32(sacc[mt][nt], qf[mt][ks], bf[nt]);
        }
#pragma unroll
        for (int mt = 0; mt < 2; mt++)
#pragma unroll
            for (int nt = 0; nt < 4; nt++) {
                rsm[mt][0] += __expf(sacc[mt][nt][0]) + __expf(sacc[mt][nt][1]);
                rsm[mt][1] += __expf(sacc[mt][nt][2]) + __expf(sacc[mt][nt][3]);
            }
    }
    float lsum[2][2];
#pragma unroll
    for (int mt = 0; mt < 2; mt++)
#pragma unroll
        for (int j = 0; j < 2; j++) {
            float v = rsm[mt][j];
            v += __shfl_xor_sync(0xffffffffu, v, 1);
            v += __shfl_xor_sync(0xffffffffu, v, 2);
            lsum[mt][j] = __logf(v);
        }

    // ---- pass B: normalized E (regs) -> STG + EV MMA directly ----
    float oacc[2][4][4];
#pragma unroll
    for (int mt = 0; mt < 2; mt++)
#pragma unroll
        for (int ct = 0; ct < 4; ct++)
#pragma unroll
            for (int i = 0; i < 4; i++) oacc[mt][ct][i] = 0.f;

    for (int c0 = 0; c0 < WIN; c0 += 32) {
        float sacc[2][4][4];
#pragma unroll
        for (int mt = 0; mt < 2; mt++)
#pragma unroll
            for (int nt = 0; nt < 4; nt++)
#pragma unroll
                for (int i = 0; i < 4; i++) sacc[mt][nt][i] = 0.f;
#pragma unroll
        for (int ks = 0; ks < 4; ks++) {
            uint32_t bf[4][2];
#pragma unroll
            for (int nt = 0; nt < 4; nt++) {
                int n = c0 + nt * 8 + r;
                uint2 u = *(const uint2*)&Ks[n * KST + ks * 8 + 2 * qk];
                bf[nt][0] = u.x; bf[nt][1] = u.y;
            }
#pragma unroll
            for (int mt = 0; mt < 2; mt++)
#pragma unroll
                for (int nt = 0; nt < 4; nt++)
                    mma_tf32(sacc[mt][nt], qf[mt][ks], bf[nt]);
        }

#pragma unroll
        for (int nt = 0; nt < 4; nt++) {
            uint32_t af[2][4];
#pragma unroll
            for (int mt = 0; mt < 2; mt++) {
                int m0 = w * 32 + mt * 16 + r;
                uint32_t t0 = f2tf(__expf(sacc[mt][nt][0] - lsum[mt][0]));
                uint32_t t1 = f2tf(__expf(sacc[mt][nt][1] - lsum[mt][0]));
                uint32_t t2 = f2tf(__expf(sacc[mt][nt][2] - lsum[mt][1]));
                uint32_t t3 = f2tf(__expf(sacc[mt][nt][3] - lsum[mt][1]));
                int col = nt * 8 + 2 * qk;
                uint32_t* drow = (uint32_t*)&dout[abase + (size_t)m0 * WIN + c0 + col];
                *(uint2*)drow             = make_uint2(t0, t1);
                *(uint2*)(drow + 8 * WIN) = make_uint2(t2, t3);
                af[mt][0] = t0; af[mt][1] = t2; af[mt][2] = t1; af[mt][3] = t3;
            }
#pragma unroll
            for (int ct = 0; ct < 4; ct++) {
                uint2 v = *(const uint2*)&Vs[(ct * 8 + r) * VST + c0 + nt * 8 + 2 * qk];
                uint32_t bv[2] = {v.x, v.y};
                mma_tf32(oacc[0][ct], af[0], bv);
                mma_tf32(oacc[1][ct], af[1], bv);
            }
        }
    }

    __syncthreads();   // all warps done reading Ks -> reuse as Os

    float* Os = (float*)Ks;
#pragma unroll
    for (int mt = 0; mt < 2; mt++) {
        int m0 = w * 32 + mt * 16 + r;
#pragma unroll
        for (int ct = 0; ct < 4; ct++) {
            int ch = ct * 8 + 2 * qk;
            Os[ch * VST + m0]           = oacc[mt][ct][0];
            Os[(ch + 1) * VST + m0]     = oacc[mt][ct][1];
            Os[ch * VST + m0 + 8]       = oacc[mt][ct][2];
            Os[(ch + 1) * VST + m0 + 8] = oacc[mt][ct][3];
        }
    }
    __syncthreads();

    size_t obase = (size_t)b * C_SZ * PIX + p;
#pragma unroll
    for (int cc = 0; cc < 32; cc++) {
        float acc = lbsh[cc];
#pragma unroll
        for (int ky = 0; ky < 3; ky++) {
            int rr = rr0 + ky - 1;
            if (rr < 0 || rr >= hsp) continue;
#pragma unroll
            for (int kx = 0; kx < 3; kx++) {
                int cx = cc0 + kx - 1;
                if (cx < 0 || cx >= wsp) continue;
                acc += lwsh[cc][ky * 3 + kx] * __uint_as_float(Vs[cc * VST + rr * wsp + cx]);
            }
        }
        int ch = br * 128 + cc * 4 + hd;
        xcat[obase + (size_t)ch * PIX] = __uint_as_float(f2tf(Os[cc * VST + s] + acc));
    }
}

// ---------------------------------------------------------------------------
extern "C" void kernel_launch(void* const* d_in, const int* in_sizes, int n_in,
                              void* d_out, int out_size) {
    const float* x       = (const float*)d_in[0];
    const float* ln_g    = (const float*)d_in[1];
    const float* ln_b    = (const float*)d_in[2];
    const float* w_qkv   = (const float*)d_in[3];
    const float* proj_w  = (const float*)d_in[4];
    const float* proj_b  = (const float*)d_in[5];
    const float* lepe_w1 = (const float*)d_in[6];
    const float* lepe_b1 = (const float*)d_in[7];
    const float* lepe_w2 = (const float*)d_in[8];
    const float* lepe_b2 = (const float*)d_in[9];
    float* out = (float*)d_out;

    float *xn, *qkv, *xcat;
    uint32_t *wq, *wp;
    cudaGetSymbolAddress((void**)&xn,   g_xn);
    cudaGetSymbolAddress((void**)&qkv,  g_qkv);
    cudaGetSymbolAddress((void**)&xcat, g_xcat);
    cudaGetSymbolAddress((void**)&wq,   g_wq);
    cudaGetSymbolAddress((void**)&wp,   g_wp);

    size_t gemm_smem = (size_t)(3 * (STAGE_A + STAGE_B)) * 4;       // ~111KB
    cudaFuncSetAttribute(gemm_tf32, cudaFuncAttributeMaxDynamicSharedMemorySize,
                         (int)gemm_smem);
    size_t attn_smem = (size_t)(256 * KST + 32 * VST) * 4;          // ~73KB
    cudaFuncSetAttribute(attn_kernel, cudaFuncAttributeMaxDynamicSharedMemorySize,
                         (int)attn_smem);

    // 0. weight prep
    wprep<<<1024, 256>>>(w_qkv, proj_w, wq, wp);

    // 1. LayerNorm (vectorized; emits tf32 bits)
    ln_kernel<<<L_TOT / 64, 256>>>(x, ln_g, ln_b, xn);

    // 2. QKV GEMM (window-major output for lower-half channels)
    {
        dim3 grid((3 * C_SZ) / 128, L_TOT / 128);
        gemm_tf32<<<grid, 128, gemm_smem>>>((const uint32_t*)xn, wq, nullptr, qkv,
                                            C_SZ, 3 * C_SZ, 0, 1);
    }

    // 3. Attention + LePE
    {
        dim3 grid(NWIN, HEADS, 2);
        attn_kernel<<<grid, 256, attn_smem>>>(qkv, lepe_w1, lepe_b1, lepe_w2, lepe_b2,
                                              xcat, out);
    }

    // 4. Projection GEMM + bias
    {
        dim3 grid(C_SZ / 128, L_TOT / 128);
        gemm_tf32<<<grid, 128, gemm_smem>>>((const uint32_t*)xcat, wp, proj_b, out,
                                            C_SZ, C_SZ, 1, 0);
    }
    (void)in_sizes; (void)n_in; (void)out_size;
}

// round 11
// speedup vs baseline: 1.1287x; 1.1287x over previous
#include <cuda_runtime.h>
#include <math.h>
#include <stdint.h>

// Problem constants
#define B_SZ   8
#define C_SZ   256
#define H_SZ   64
#define W_SZ   64
#define PIX    4096          // H*W
#define L_TOT  32768         // B*H*W
#define HEADS  4
#define WIN    256           // window size (positions)
#define NWIN   128           // windows per branch (B*16)
#define SCALE  0.125f        // (256/4)^-0.5
#define LN_EPS 1e-4f

#define OUT_ELEMS  ((size_t)B_SZ * C_SZ * PIX)          // 8388608
#define ATTN_ELEMS ((size_t)NWIN * HEADS * WIN * WIN)   // 8388608

// Scratch (device globals — no allocation allowed)
__device__ float    g_xn[(size_t)B_SZ * C_SZ * PIX];       // LN out (tf32 bits)
__device__ float    g_qkv[(size_t)B_SZ * 3 * C_SZ * PIX];  // qkv (window-major for ch<128)
__device__ float    g_xcat[(size_t)B_SZ * C_SZ * PIX];     // attn out (tf32 bits)
__device__ uint32_t g_wq[768 * 256];                       // W_qkv tf32, k-pair permuted
__device__ uint32_t g_wp[256 * 256];                       // W_proj tf32, k-pair permuted

// ---------------------------------------------------------------------------
__device__ __forceinline__ uint32_t f2tf(float f) {
    uint32_t r;
    asm("cvt.rna.tf32.f32 %0, %1;" : "=r"(r) : "f"(f));
    return r;
}

__device__ __forceinline__ void mma_tf32(float* d, const uint32_t* a, const uint32_t* b) {
    asm("mma.sync.aligned.m16n8k8.row.col.f32.tf32.tf32.f32 "
        "{%0,%1,%2,%3},{%4,%5,%6,%7},{%8,%9},{%0,%1,%2,%3};"
        : "+f"(d[0]), "+f"(d[1]), "+f"(d[2]), "+f"(d[3])
        : "r"(a[0]), "r"(a[1]), "r"(a[2]), "r"(a[3]), "r"(b[0]), "r"(b[1]));
}

__device__ __forceinline__ void cp16(void* dst, const void* src) {
    uint32_t d = (uint32_t)__cvta_generic_to_shared(dst);
    asm volatile("cp.async.cg.shared.global [%0], [%1], 16;" :: "r"(d), "l"(src));
}
__device__ __forceinline__ void cp_commit() {
    asm volatile("cp.async.commit_group;");
}

// ---------------------------------------------------------------------------
// Weight prep: tf32 convert + k-pair permutation (phys c <- logical l)
// ---------------------------------------------------------------------------
__global__ void wprep(const float* __restrict__ wqkv, const float* __restrict__ wproj,
                      uint32_t* __restrict__ wq, uint32_t* __restrict__ wp) {
    int idx = blockIdx.x * 256 + threadIdx.x;
    int j = idx >> 8, c = idx & 255;
    int l = (c & ~7) + ((c >> 1) & 3) + (c & 1) * 4;
    if (j < 768) wq[idx] = f2tf(wqkv[j * 256 + l]);
    else         wp[(j - 768) * 256 + c] = f2tf(wproj[(j - 768) * 256 + l]);
}

// ---------------------------------------------------------------------------
// LayerNorm over C per pixel (round-9 scalar version; emits tf32 bits).
// ---------------------------------------------------------------------------
__global__ void ln_kernel(const float* __restrict__ x,
                          const float* __restrict__ g,
                          const float* __restrict__ be,
                          float* __restrict__ xnT) {
    int px0  = blockIdx.x * 32;
    int b    = px0 >> 12;
    int p0   = px0 & (PIX - 1);
    int lane = threadIdx.x & 31;
    int ty   = threadIdx.x >> 5;

    const float* xb = x + (size_t)b * C_SZ * PIX + p0 + lane;
    float v[32];
    float sum = 0.f, sq = 0.f;
#pragma unroll
    for (int i = 0; i < 32; i++) {
        int c = ty + i * 8;
        float t = xb[(size_t)c * PIX];
        v[i] = t;
        sum += t;
        sq  += t * t;
    }
    __shared__ float rs[2][8][32];
    __shared__ float mu_s[32], rstd_s[32];
    rs[0][ty][lane] = sum;
    rs[1][ty][lane] = sq;
    __syncthreads();
    if (ty == 0) {
        float s1 = 0.f, s2 = 0.f;
#pragma unroll
        for (int k = 0; k < 8; k++) { s1 += rs[0][k][lane]; s2 += rs[1][k][lane]; }
        float mu  = s1 * (1.0f / C_SZ);
        float var = s2 * (1.0f / C_SZ) - mu * mu;
        mu_s[lane]   = mu;
        rstd_s[lane] = rsqrtf(var + LN_EPS);
    }
    __syncthreads();
    float mu = mu_s[lane], rstd = rstd_s[lane];
    float* ob = xnT + (size_t)b * C_SZ * PIX + p0 + lane;
#pragma unroll
    for (int i = 0; i < 32; i++) {
        int c = ty + i * 8;
        ob[(size_t)c * PIX] = __uint_as_float(f2tf((v[i] - mu) * rstd * g[c] + be[c]));
    }
}

// ---------------------------------------------------------------------------
// tf32 GEMM: CTA 128(j) x 128(pix), 256 threads (8 warps, 64x32 warp tile),
// 3-stage cp.async, 2 CTAs/SM -> 4 warps per SMSP for MMA interleave.
// ---------------------------------------------------------------------------
#define ASTR 40
#define BSTR 136
#define STAGE_A (128 * ASTR)
#define STAGE_B (32 * BSTR)

__global__ __launch_bounds__(256, 2)
void gemm_tf32(const uint32_t* __restrict__ ATu,
               const uint32_t* __restrict__ Wu,
               const float* __restrict__ bias,
               float* __restrict__ outT,
               int CA, int CO, int hasb, int permq) {
    extern __shared__ uint32_t smu[];
    uint32_t* As = smu;                    // 3 stages
    uint32_t* Bs = smu + 3 * STAGE_A;      // 3 stages

    int tid = threadIdx.x;
    int j0  = blockIdx.x * 128;
    int l0  = blockIdx.y * 128;
    int b   = l0 >> 12;
    int p0  = l0 & (PIX - 1);

    const uint32_t* Ab = ATu + (size_t)b * CA * PIX + p0;
    int lane = tid & 31;
    int w    = tid >> 5;
    int wm   = w & 1;        // M half (64)
    int wn   = w >> 1;       // N quarter (32)
    int r    = lane >> 2;
    int qk   = lane & 3;

    int arow = tid >> 1, aoff = (tid & 1) * 16;   // A loader: 128 rows x 32 cols
    int brow = tid >> 3, bcol = (tid & 7) * 16;   // B loader: 32 rows x 128 cols

    float d[4][4][4];
#pragma unroll
    for (int mt = 0; mt < 4; mt++)
#pragma unroll
        for (int nt = 0; nt < 4; nt++)
#pragma unroll
            for (int i = 0; i < 4; i++) d[mt][nt][i] = 0.f;

    const int NC = CA / 32;

    auto issue = [&](int c0, int buf) {
        uint32_t* Ad = As + buf * STAGE_A + arow * ASTR + aoff;
        const uint32_t* Asrc = Wu + (size_t)(j0 + arow) * CA + c0 + aoff;
#pragma unroll
        for (int i = 0; i < 4; i++) cp16(Ad + i * 4, Asrc + i * 4);
        uint32_t* Bd = Bs + buf * STAGE_B + brow * BSTR + bcol;
        const uint32_t* Bsrc = Ab + (size_t)(c0 + brow) * PIX + bcol;
#pragma unroll
        for (int i = 0; i < 4; i++) cp16(Bd + i * 4, Bsrc + i * 4);
        cp_commit();
    };

    issue(0, 0);
    if (NC > 1) issue(32, 1);

    for (int ic = 0; ic < NC; ic++) {
        if (ic + 2 < NC) {
            issue((ic + 2) * 32, (ic + 2) % 3);
            asm volatile("cp.async.wait_group 2;");
        } else if (ic + 1 < NC) {
            asm volatile("cp.async.wait_group 1;");
        } else {
            asm volatile("cp.async.wait_group 0;");
        }
        __syncthreads();

        const uint32_t* Abs = As + (ic % 3) * STAGE_A;
        const uint32_t* Bbs = Bs + (ic % 3) * STAGE_B;
#pragma unroll
        for (int ks = 0; ks < 4; ks++) {
            int kk8 = ks * 8;
            uint32_t afr[4][4];
#pragma unroll
            for (int mt = 0; mt < 4; mt++) {
                int m0 = wm * 64 + mt * 16 + r;
                uint2 u0 = *(const uint2*)&Abs[m0 * ASTR + kk8 + 2 * qk];
                uint2 u1 = *(const uint2*)&Abs[(m0 + 8) * ASTR + kk8 + 2 * qk];
                afr[mt][0] = u0.x; afr[mt][1] = u1.x;
                afr[mt][2] = u0.y; afr[mt][3] = u1.y;
            }
            uint32_t bfr[4][2];
#pragma unroll
            for (int nt = 0; nt < 4; nt++) {
                int n = wn * 32 + nt * 8 + r;
                bfr[nt][0] = Bbs[(kk8 + qk) * BSTR + n];
                bfr[nt][1] = Bbs[(kk8 + qk + 4) * BSTR + n];
            }
#pragma unroll
            for (int mt = 0; mt < 4; mt++)
#pragma unroll
                for (int nt = 0; nt < 4; nt++)
                    mma_tf32(d[mt][nt], afr[mt], bfr[nt]);
        }
        __syncthreads();
    }

    int prm = permq && ((j0 & 128) == 0);   // lower-half channels -> branch-0 perm
    float* obase = outT + (size_t)b * CO * PIX;
#pragma unroll
    for (int mt = 0; mt < 4; mt++) {
        int j = j0 + wm * 64 + mt * 16 + r;
        float bv0 = hasb ? bias[j]     : 0.f;
        float bv1 = hasb ? bias[j + 8] : 0.f;
#pragma unroll
        for (int nt = 0; nt < 4; nt++) {
            int p2 = p0 + wn * 32 + nt * 8 + qk * 2;
            int pp = prm ? (((p2 & 63) >> 2) * 256 + ((p2 >> 6) << 2) + (p2 & 3)) : p2;
            float* o = obase + (size_t)j * PIX + pp;
            *(float2*)o = make_float2(d[mt][nt][0] + bv0, d[mt][nt][1] + bv0);
            *(float2*)(o + 8 * PIX) = make_float2(d[mt][nt][2] + bv1, d[mt][nt][3] + bv1);
        }
    }
}

// ---------------------------------------------------------------------------
// Two-pass MMA attention + LePE (unchanged from round 9).
// dyn smem: Ks [256*40], Vs [32*264]  (~73KB)
// ---------------------------------------------------------------------------
#define KST 40
#define VST 264

__global__ __launch_bounds__(256, 2)
void attn_kernel(const float* __restrict__ qkvT,
                 const float* __restrict__ lw1,
                 const float* __restrict__ lb1,
                 const float* __restrict__ lw2,
                 const float* __restrict__ lb2,
                 float* __restrict__ xcat,
                 float* __restrict__ dout) {
    int br   = blockIdx.z;
    int hd   = blockIdx.y;
    int widx = blockIdx.x;
    int b    = widx >> 4;
    int wg   = widx & 15;
    int s    = threadIdx.x;
    int lane = s & 31;
    int w    = s >> 5;
    int r    = lane >> 2;
    int qk   = lane & 3;

    int hsp, wsp, p, rr0, cc0;
    if (br == 0) {
        hsp = 64; wsp = 4;
        rr0 = s >> 2; cc0 = s & 3;
        p = rr0 * W_SZ + wg * 4 + cc0;
    } else {
        hsp = 4; wsp = 64;
        rr0 = s >> 6; cc0 = s & 63;
        p = (wg * 4 + rr0) * W_SZ + cc0;
    }
    const float* lw = br ? lw2 : lw1;
    const float* lb = br ? lb2 : lb1;

    extern __shared__ uint32_t smA[];
    uint32_t* Ks = smA;                  // [256][40] pair-permuted cols (->Os)
    uint32_t* Vs = smA + 256 * KST;      // [32][264]
    __shared__ float lwsh[32][9];
    __shared__ float lbsh[32];

    size_t base = (size_t)b * 3 * C_SZ * PIX + wg * 256;

    // ---- coalesced K/V load (lane = 8*ci + si; conflict-free STS) ----
    {
        int ci = lane >> 3;
        int si = lane & 7;
#pragma unroll
        for (int g = 0; g < 8; g++) {
            int cc = 4 * g + ci;
            int ch = br * 128 + cc * 4 + hd;
            int sg = (cc & 24) + 2 * (cc & 3) + ((cc >> 2) & 1);  // K col perm
            const float* qp = qkvT + base + (size_t)ch * PIX;
#pragma unroll
            for (int u = 0; u < 4; u++) {
                int s2 = w * 32 + u * 8 + si;
                Ks[s2 * KST + sg] = f2tf(qp[(size_t)C_SZ * PIX + s2]);
                Vs[cc * VST + s2] = f2tf(qp[(size_t)(2 * C_SZ) * PIX + s2]);
            }
        }
    }
    for (int i = s; i < 32 * 9; i += 256) {
        int cc = i / 9, kk = i % 9;
        lwsh[cc][kk] = lw[(size_t)(cc * 4 + hd) * 9 + kk];
    }
    if (s < 32) lbsh[s] = lb[s * 4 + hd];

    // ---- Q fragments direct from gmem ----
    uint32_t qf[2][4][4];
#pragma unroll
    for (int ks = 0; ks < 4; ks++) {
        int kk = ks * 8 + qk;
        const float* q0 = qkvT + base + (size_t)(br * 128 + kk * 4 + hd) * PIX;
        const float* q1 = qkvT + base + (size_t)(br * 128 + (kk + 4) * 4 + hd) * PIX;
#pragma unroll
        for (int mt = 0; mt < 2; mt++) {
            int m0 = w * 32 + mt * 16 + r;
            qf[mt][ks][0] = f2tf(q0[m0] * SCALE);
            qf[mt][ks][1] = f2tf(q0[m0 + 8] * SCALE);
            qf[mt][ks][2] = f2tf(q1[m0] * SCALE);
            qf[mt][ks][3] = f2tf(q1[m0 + 8] * SCALE);
        }
    }
    __syncthreads();

    size_t abase = OUT_ELEMS + (size_t)br * ATTN_ELEMS
                 + (size_t)(widx * HEADS + hd) * WIN * WIN;

    // ---- pass A: row sums ----
    float rsm[2][2] = {{0.f, 0.f}, {0.f, 0.f}};
    for (int c0 = 0; c0 < WIN; c0 += 32) {
        float sacc[2][4][4];
#pragma unroll
        for (int mt = 0; mt < 2; mt++)
#pragma unroll
            for (int nt = 0; nt < 4; nt++)
#pragma unroll
                for (int i = 0; i < 4; i++) sacc[mt][nt][i] = 0.f;
#pragma unroll
        for (int ks = 0; ks < 4; ks++) {
            uint32_t bf[4][2];
#pragma unroll
            for (int nt = 0; nt < 4; nt++) {
                int n = c0 + nt * 8 + r;
                uint2 u = *(const uint2*)&Ks[n * KST + ks * 8 + 2 * qk];
                bf[nt][0] = u.x; bf[nt][1] = u.y;
            }
#pragma unroll
            for (int mt = 0; mt < 2; mt++)
#pragma unroll
                for (int nt = 0; nt < 4; nt++)
                    mma_tf32(sacc[mt][nt], qf[mt][ks], bf[nt]);
        }
#pragma unroll
        for (int mt = 0; mt < 2; mt++)
#pragma unroll
            for (int nt = 0; nt < 4; nt++) {
                rsm[mt][0] += __expf(sacc[mt][nt][0]) + __expf(sacc[mt][nt][1]);
                rsm[mt][1] += __expf(sacc[mt][nt][2]) + __expf(sacc[mt][nt][3]);
            }
    }
    float lsum[2][2];
#pragma unroll
    for (int mt = 0; mt < 2; mt++)
#pragma unroll
        for (int j = 0; j < 2; j++) {
            float v = rsm[mt][j];
            v += __shfl_xor_sync(0xffffffffu, v, 1);
            v += __shfl_xor_sync(0xffffffffu, v, 2);
            lsum[mt][j] = __logf(v);
        }

    // ---- pass B: normalized E (regs) -> STG + EV MMA directly ----
    float oacc[2][4][4];
#pragma unroll
    for (int mt = 0; mt < 2; mt++)
#pragma unroll
        for (int ct = 0; ct < 4; ct++)
#pragma unroll
            for (int i = 0; i < 4; i++) oacc[mt][ct][i] = 0.f;

    for (int c0 = 0; c0 < WIN; c0 += 32) {
        float sacc[2][4][4];
#pragma unroll
        for (int mt = 0; mt < 2; mt++)
#pragma unroll
            for (int nt = 0; nt < 4; nt++)
#pragma unroll
                for (int i = 0; i < 4; i++) sacc[mt][nt][i] = 0.f;
#pragma unroll
        for (int ks = 0; ks < 4; ks++) {
            uint32_t bf[4][2];
#pragma unroll
            for (int nt = 0; nt < 4; nt++) {
                int n = c0 + nt * 8 + r;
                uint2 u = *(const uint2*)&Ks[n * KST + ks * 8 + 2 * qk];
                bf[nt][0] = u.x; bf[nt][1] = u.y;
            }
#pragma unroll
            for (int mt = 0; mt < 2; mt++)
#pragma unroll
                for (int nt = 0; nt < 4; nt++)
                    mma_tf32(sacc[mt][nt], qf[mt][ks], bf[nt]);
        }

#pragma unroll
        for (int nt = 0; nt < 4; nt++) {
            uint32_t af[2][4];
#pragma unroll
            for (int mt = 0; mt < 2; mt++) {
                int m0 = w * 32 + mt * 16 + r;
                uint32_t t0 = f2tf(__expf(sacc[mt][nt][0] - lsum[mt][0]));
                uint32_t t1 = f2tf(__expf(sacc[mt][nt][1] - lsum[mt][0]));
                uint32_t t2 = f2tf(__expf(sacc[mt][nt][2] - lsum[mt][1]));
                uint32_t t3 = f2tf(__expf(sacc[mt][nt][3] - lsum[mt][1]));
                int col = nt * 8 + 2 * qk;
                uint32_t* drow = (uint32_t*)&dout[abase + (size_t)m0 * WIN + c0 + col];
                *(uint2*)drow             = make_uint2(t0, t1);
                *(uint2*)(drow + 8 * WIN) = make_uint2(t2, t3);
                af[mt][0] = t0; af[mt][1] = t2; af[mt][2] = t1; af[mt][3] = t3;
            }
#pragma unroll
            for (int ct = 0; ct < 4; ct++) {
                uint2 v = *(const uint2*)&Vs[(ct * 8 + r) * VST + c0 + nt * 8 + 2 * qk];
                uint32_t bv[2] = {v.x, v.y};
                mma_tf32(oacc[0][ct], af[0], bv);
                mma_tf32(oacc[1][ct], af[1], bv);
            }
        }
    }

    __syncthreads();   // all warps done reading Ks -> reuse as Os

    float* Os = (float*)Ks;
#pragma unroll
    for (int mt = 0; mt < 2; mt++) {
        int m0 = w * 32 + mt * 16 + r;
#pragma unroll
        for (int ct = 0; ct < 4; ct++) {
            int ch = ct * 8 + 2 * qk;
            Os[ch * VST + m0]           = oacc[mt][ct][0];
            Os[(ch + 1) * VST + m0]     = oacc[mt][ct][1];
            Os[ch * VST + m0 + 8]       = oacc[mt][ct][2];
            Os[(ch + 1) * VST + m0 + 8] = oacc[mt][ct][3];
        }
    }
    __syncthreads();

    size_t obase = (size_t)b * C_SZ * PIX + p;
#pragma unroll
    for (int cc = 0; cc < 32; cc++) {
        float acc = lbsh[cc];
#pragma unroll
        for (int ky = 0; ky < 3; ky++) {
            int rr = rr0 + ky - 1;
            if (rr < 0 || rr >= hsp) continue;
#pragma unroll
            for (int kx = 0; kx < 3; kx++) {
                int cx = cc0 + kx - 1;
                if (cx < 0 || cx >= wsp) continue;
                acc += lwsh[cc][ky * 3 + kx] * __uint_as_float(Vs[cc * VST + rr * wsp + cx]);
            }
        }
        int ch = br * 128 + cc * 4 + hd;
        xcat[obase + (size_t)ch * PIX] = __uint_as_float(f2tf(Os[cc * VST + s] + acc));
    }
}

// ---------------------------------------------------------------------------
extern "C" void kernel_launch(void* const* d_in, const int* in_sizes, int n_in,
                              void* d_out, int out_size) {
    const float* x       = (const float*)d_in[0];
    const float* ln_g    = (const float*)d_in[1];
    const float* ln_b    = (const float*)d_in[2];
    const float* w_qkv   = (const float*)d_in[3];
    const float* proj_w  = (const float*)d_in[4];
    const float* proj_b  = (const float*)d_in[5];
    const float* lepe_w1 = (const float*)d_in[6];
    const float* lepe_b1 = (const float*)d_in[7];
    const float* lepe_w2 = (const float*)d_in[8];
    const float* lepe_b2 = (const float*)d_in[9];
    float* out = (float*)d_out;

    float *xn, *qkv, *xcat;
    uint32_t *wq, *wp;
    cudaGetSymbolAddress((void**)&xn,   g_xn);
    cudaGetSymbolAddress((void**)&qkv,  g_qkv);
    cudaGetSymbolAddress((void**)&xcat, g_xcat);
    cudaGetSymbolAddress((void**)&wq,   g_wq);
    cudaGetSymbolAddress((void**)&wp,   g_wp);

    size_t gemm_smem = (size_t)(3 * (STAGE_A + STAGE_B)) * 4;       // ~111KB
    cudaFuncSetAttribute(gemm_tf32, cudaFuncAttributeMaxDynamicSharedMemorySize,
                         (int)gemm_smem);
    size_t attn_smem = (size_t)(256 * KST + 32 * VST) * 4;          // ~73KB
    cudaFuncSetAttribute(attn_kernel, cudaFuncAttributeMaxDynamicSharedMemorySize,
                         (int)attn_smem);

    // 0. weight prep
    wprep<<<1024, 256>>>(w_qkv, proj_w, wq, wp);

    // 1. LayerNorm (emits tf32 bits)
    ln_kernel<<<L_TOT / 32, 256>>>(x, ln_g, ln_b, xn);

    // 2. QKV GEMM (window-major output for lower-half channels)
    {
        dim3 grid((3 * C_SZ) / 128, L_TOT / 128);
        gemm_tf32<<<grid, 256, gemm_smem>>>((const uint32_t*)xn, wq, nullptr, qkv,
                                            C_SZ, 3 * C_SZ, 0, 1);
    }

    // 3. Attention + LePE
    {
        dim3 grid(NWIN, HEADS, 2);
        attn_kernel<<<grid, 256, attn_smem>>>(qkv, lepe_w1, lepe_b1, lepe_w2, lepe_b2,
                                              xcat, out);
    }

    // 4. Projection GEMM + bias
    {
        dim3 grid(C_SZ / 128, L_TOT / 128);
        gemm_tf32<<<grid, 256, gemm_smem>>>((const uint32_t*)xcat, wp, proj_b, out,
                                            C_SZ, C_SZ, 1, 0);
    }
    (void)in_sizes; (void)n_in; (void)out_size;
}